// round 1
// baseline (speedup 1.0000x reference)
#include <cuda_runtime.h>

#define C        384
#define NQKV     1152
#define NWIN     2048   // 32 images * 64 windows
#define D        64     // tokens per window

// Scratch (device globals are the sanctioned scratch mechanism).
__device__ float g_qkv[(size_t)NWIN * D * NQKV];  // [m][3*384] qkv
__device__ float g_ctx[(size_t)NWIN * D * C];     // [m][384] attention output

// Force module load (and thus global allocation) at program init, before the
// harness takes its memory checkpoint around kernel_launch.
namespace {
struct ForceLoad {
    ForceLoad() {
        void* p = nullptr;
        cudaGetSymbolAddress(&p, g_qkv);
        cudaGetSymbolAddress(&p, g_ctx);
    }
};
ForceLoad g_force_load;
}

// ---------------------------------------------------------------------------
// Shared 64x128 GEMM body: Acc[64,128] += A[64,384] * W[384, ldw](cols n0..n0+127)
// A rows come through per-row pointers (handles roll/window gather).
// 256 threads, thread tile 8(m) x 4(n).
// ---------------------------------------------------------------------------
__device__ __forceinline__ void gemm_body(
    const float* const* rowptr, const float* __restrict__ w, int ldw,
    int n0, int tid, float acc[8][4],
    float (*As)[32], float (*Bs)[128])
{
    const int tx = tid & 31;
    const int ty = tid >> 5;
    for (int k0 = 0; k0 < C; k0 += 32) {
        __syncthreads();
        // Load A tile [64 x 32]
#pragma unroll
        for (int s = 0; s < 2; ++s) {
            int slot = tid + 256 * s;
            int row  = slot >> 3;
            int kq   = (slot & 7) << 2;
            *(float4*)&As[row][kq] = *(const float4*)(rowptr[row] + k0 + kq);
        }
        // Load B tile [32 x 128]
#pragma unroll
        for (int s = 0; s < 4; ++s) {
            int slot = tid + 256 * s;
            int kk   = slot >> 5;
            int cq   = (slot & 31) << 2;
            *(float4*)&Bs[kk][cq] =
                *(const float4*)(w + (size_t)(k0 + kk) * ldw + n0 + cq);
        }
        __syncthreads();
#pragma unroll 8
        for (int k = 0; k < 32; ++k) {
            float4 b = *(const float4*)&Bs[k][tx << 2];
            float a[8];
#pragma unroll
            for (int i = 0; i < 8; ++i) a[i] = As[(ty << 3) + i][k];
#pragma unroll
            for (int i = 0; i < 8; ++i) {
                acc[i][0] = fmaf(a[i], b.x, acc[i][0]);
                acc[i][1] = fmaf(a[i], b.y, acc[i][1]);
                acc[i][2] = fmaf(a[i], b.z, acc[i][2]);
                acc[i][3] = fmaf(a[i], b.w, acc[i][3]);
            }
        }
    }
}

// ---------------------------------------------------------------------------
// Kernel 1: QKV projection. grid = (9, 2048). One window (64 rows) per CTA.y.
// A row t of window n gathers x[img, (wr*8+r_in+4)&63, (wc*8+c_in+4)&63, :].
// ---------------------------------------------------------------------------
__global__ __launch_bounds__(256, 2) void qkv_kernel(
    const float* __restrict__ x, const float* __restrict__ w,
    const float* __restrict__ bias)
{
    __shared__ float As[64][32];
    __shared__ float Bs[32][128];
    __shared__ const float* rowptr[64];
    const int tid = threadIdx.x;
    const int win = blockIdx.y;
    const int n0  = blockIdx.x * 128;

    if (tid < 64) {
        int img = win >> 6, wi = win & 63, wr = wi >> 3, wc = wi & 7;
        int ri = tid >> 3, ci = tid & 7;
        int gr = (wr * 8 + ri + 4) & 63;
        int gc = (wc * 8 + ci + 4) & 63;
        rowptr[tid] = x + (((size_t)img * 64 + gr) * 64 + gc) * C;
    }

    float acc[8][4];
#pragma unroll
    for (int i = 0; i < 8; ++i)
#pragma unroll
        for (int j = 0; j < 4; ++j) acc[i][j] = 0.f;

    gemm_body(rowptr, w, NQKV, n0, tid, acc, As, Bs);

    const int tx = tid & 31, ty = tid >> 5;
    const float4 bb = *(const float4*)&bias[n0 + (tx << 2)];
#pragma unroll
    for (int i = 0; i < 8; ++i) {
        size_t m = (size_t)win * D + (ty << 3) + i;
        float4 o = make_float4(acc[i][0] + bb.x, acc[i][1] + bb.y,
                               acc[i][2] + bb.z, acc[i][3] + bb.w);
        *(float4*)&g_qkv[m * NQKV + n0 + (tx << 2)] = o;
    }
}

// ---------------------------------------------------------------------------
// Kernel 2: attention per (window, head). grid = (2048, 12), 256 threads.
// scores = q*scale @ k^T + bias_table[(qr+qc)-(kr+kc)+29, h] + shift-mask
// softmax rows, ctx = P @ v.
// ---------------------------------------------------------------------------
__global__ __launch_bounds__(256) void attn_kernel(const float* __restrict__ bt)
{
    __shared__ float qs[64][32];
    __shared__ float ks[64][36];
    __shared__ float vs[64][36];
    __shared__ float ps[64][68];
    __shared__ int   s_sum[64];
    __shared__ int   s_regn[64];
    __shared__ float s_bias[32];

    const int tid = threadIdx.x;
    const int win = blockIdx.x;
    const int h   = blockIdx.y;
    const float scale = 0.17677669529663687f;  // 1/sqrt(32)

    if (tid < 64) {
        int wi = win & 63, wr = wi >> 3, wc = wi & 7;
        int ri = tid >> 3, ci = tid & 7;
        s_sum[tid] = ri + ci;
        // region id on shifted-image coords (mask grid == window grid)
        int gr = wr * 8 + ri, gc = wc * 8 + ci;
        int rb = gr < 56 ? 0 : (gr < 60 ? 1 : 2);
        int cb = gc < 56 ? 0 : (gc < 60 ? 1 : 2);
        s_regn[tid] = rb * 3 + cb;
    }
    if (tid >= 64 && tid < 93) {
        int u = tid - 64;                    // bias idx range is [15, 43]
        s_bias[u] = bt[(u + 15) * 12 + h];
    }

    const size_t base = ((size_t)win * D) * NQKV + (size_t)h * 32;
#pragma unroll
    for (int s = 0; s < 2; ++s) {
        int slot = tid + 256 * s;
        int row  = slot >> 3;
        int eq   = (slot & 7) << 2;
        const float* src = &g_qkv[base + (size_t)row * NQKV + eq];
        float4 q4 = *(const float4*)(src);
        q4.x *= scale; q4.y *= scale; q4.z *= scale; q4.w *= scale;
        *(float4*)&qs[row][eq] = q4;
        *(float4*)&ks[row][eq] = *(const float4*)(src + 384);
        *(float4*)&vs[row][eq] = *(const float4*)(src + 768);
    }
    __syncthreads();

    const int i  = tid >> 2;   // query row, 4 threads per row
    const int jg = tid & 3;
    float q[32];
#pragma unroll
    for (int e = 0; e < 32; ++e) q[e] = qs[i][e];
    const int isum  = s_sum[i];
    const int iregn = s_regn[i];

    float sc[16];
    float mx = -1e30f;
#pragma unroll
    for (int jj = 0; jj < 16; ++jj) {
        int j = (jj << 2) + jg;
        float acc = 0.f;
#pragma unroll
        for (int e = 0; e < 32; e += 4) {
            float4 k4 = *(const float4*)&ks[j][e];
            acc = fmaf(q[e],     k4.x, acc);
            acc = fmaf(q[e + 1], k4.y, acc);
            acc = fmaf(q[e + 2], k4.z, acc);
            acc = fmaf(q[e + 3], k4.w, acc);
        }
        acc += s_bias[isum - s_sum[j] + 14];
        if (iregn != s_regn[j]) acc -= 100.f;
        sc[jj] = acc;
        mx = fmaxf(mx, acc);
    }
    mx = fmaxf(mx, __shfl_xor_sync(0xffffffffu, mx, 1));
    mx = fmaxf(mx, __shfl_xor_sync(0xffffffffu, mx, 2));

    float sum = 0.f;
#pragma unroll
    for (int jj = 0; jj < 16; ++jj) {
        float e = __expf(sc[jj] - mx);
        sc[jj] = e;
        sum += e;
    }
    sum += __shfl_xor_sync(0xffffffffu, sum, 1);
    sum += __shfl_xor_sync(0xffffffffu, sum, 2);
    float inv = 1.f / sum;
#pragma unroll
    for (int jj = 0; jj < 16; ++jj) ps[i][(jj << 2) + jg] = sc[jj] * inv;
    __syncthreads();

    // out[i][e0..e0+7] = sum_j P[i][j] * v[j][e]
    const int e0 = (tid & 3) << 3;
    float o[8];
#pragma unroll
    for (int e = 0; e < 8; ++e) o[e] = 0.f;
#pragma unroll 16
    for (int j = 0; j < 64; ++j) {
        float p = ps[i][j];
        float4 v0 = *(const float4*)&vs[j][e0];
        float4 v1 = *(const float4*)&vs[j][e0 + 4];
        o[0] = fmaf(p, v0.x, o[0]); o[1] = fmaf(p, v0.y, o[1]);
        o[2] = fmaf(p, v0.z, o[2]); o[3] = fmaf(p, v0.w, o[3]);
        o[4] = fmaf(p, v1.x, o[4]); o[5] = fmaf(p, v1.y, o[5]);
        o[6] = fmaf(p, v1.z, o[6]); o[7] = fmaf(p, v1.w, o[7]);
    }
    float* cp = &g_ctx[((size_t)win * D + i) * C + h * 32 + e0];
    *(float4*)cp       = make_float4(o[0], o[1], o[2], o[3]);
    *(float4*)(cp + 4) = make_float4(o[4], o[5], o[6], o[7]);
}

// ---------------------------------------------------------------------------
// Kernel 3: output projection + window-reverse + roll(+4,+4) scatter.
// grid = (3, 2048).
// ---------------------------------------------------------------------------
__global__ __launch_bounds__(256, 2) void proj_kernel(
    const float* __restrict__ w, const float* __restrict__ bias,
    float* __restrict__ out)
{
    __shared__ float As[64][32];
    __shared__ float Bs[32][128];
    __shared__ const float* rowptr[64];
    __shared__ float* outptr[64];
    const int tid = threadIdx.x;
    const int win = blockIdx.y;
    const int n0  = blockIdx.x * 128;

    if (tid < 64) {
        rowptr[tid] = &g_ctx[((size_t)win * D + tid) * C];
        int img = win >> 6, wi = win & 63, wr = wi >> 3, wc = wi & 7;
        int ri = tid >> 3, ci = tid & 7;
        int gr = (wr * 8 + ri + 4) & 63;   // window-reverse then roll(+4) == +4 mod 64
        int gc = (wc * 8 + ci + 4) & 63;
        outptr[tid] = out + (((size_t)img * 64 + gr) * 64 + gc) * C;
    }

    float acc[8][4];
#pragma unroll
    for (int i = 0; i < 8; ++i)
#pragma unroll
        for (int j = 0; j < 4; ++j) acc[i][j] = 0.f;

    gemm_body(rowptr, w, C, n0, tid, acc, As, Bs);

    const int tx = tid & 31, ty = tid >> 5;
    const float4 bb = *(const float4*)&bias[n0 + (tx << 2)];
#pragma unroll
    for (int i = 0; i < 8; ++i) {
        float4 o = make_float4(acc[i][0] + bb.x, acc[i][1] + bb.y,
                               acc[i][2] + bb.z, acc[i][3] + bb.w);
        *(float4*)(outptr[(ty << 3) + i] + n0 + (tx << 2)) = o;
    }
}

// ---------------------------------------------------------------------------
extern "C" void kernel_launch(void* const* d_in, const int* in_sizes, int n_in,
                              void* d_out, int out_size)
{
    (void)in_sizes; (void)n_in; (void)out_size;
    const float* x      = (const float*)d_in[0];
    const float* w_qkv  = (const float*)d_in[1];
    const float* b_qkv  = (const float*)d_in[2];
    const float* w_out  = (const float*)d_in[3];
    const float* b_out  = (const float*)d_in[4];
    const float* btab   = (const float*)d_in[5];
    float* out = (float*)d_out;

    qkv_kernel <<<dim3(9, NWIN),  256>>>(x, w_qkv, b_qkv);
    attn_kernel<<<dim3(NWIN, 12), 256>>>(btab);
    proj_kernel<<<dim3(3, NWIN),  256>>>(w_out, b_out, out);
}

// round 2
// speedup vs baseline: 1.1153x; 1.1153x over previous
#include <cuda_runtime.h>

#define C        384
#define NQKV     1152
#define NWIN     2048   // 32 images * 64 windows
#define D        64     // tokens per window

// Scratch (device globals are the sanctioned scratch mechanism).
__device__ float g_qkv[(size_t)NWIN * D * NQKV];  // [m][3*384] qkv
__device__ float g_ctx[(size_t)NWIN * D * C];     // [m][384] attention output

namespace {
struct ForceLoad {
    ForceLoad() {
        void* p = nullptr;
        cudaGetSymbolAddress(&p, g_qkv);
        cudaGetSymbolAddress(&p, g_ctx);
    }
};
ForceLoad g_force_load;
}

// ---------------------------------------------------------------------------
// Packed fp32x2 helpers (Blackwell dual-fp32 pipe).
// ---------------------------------------------------------------------------
typedef unsigned long long u64;

__device__ __forceinline__ u64 pack2(float a, float b) {
    u64 r;
    asm("mov.b64 %0, {%1, %2};" : "=l"(r) : "f"(a), "f"(b));
    return r;
}
__device__ __forceinline__ void ffma2(u64& d, u64 a, u64 b) {
    asm("fma.rn.f32x2 %0, %1, %2, %0;" : "+l"(d) : "l"(a), "l"(b));
}
__device__ __forceinline__ float2 unpack2(u64 v) {
    float x, y;
    asm("mov.b64 {%0, %1}, %2;" : "=f"(x), "=f"(y) : "l"(v));
    return make_float2(x, y);
}

// ---------------------------------------------------------------------------
// Shared 64x128 GEMM body: Acc[64,128] += A[64,384] * W[384, ldw](cols n0..+127)
// A rows come through per-row pointers (handles roll/window gather).
// 256 threads, thread tile 8(m) x 4(n), accumulators packed as f32x2.
// ---------------------------------------------------------------------------
__device__ __forceinline__ void gemm_body(
    const float* const* rowptr, const float* __restrict__ w, int ldw,
    int n0, int tid, u64 acc2[8][2],
    float (*As)[32], float (*Bs)[128])
{
    const int tx = tid & 31;
    const int ty = tid >> 5;
    for (int k0 = 0; k0 < C; k0 += 32) {
        __syncthreads();
        // Load A tile [64 x 32]
#pragma unroll
        for (int s = 0; s < 2; ++s) {
            int slot = tid + 256 * s;
            int row  = slot >> 3;
            int kq   = (slot & 7) << 2;
            *(float4*)&As[row][kq] = *(const float4*)(rowptr[row] + k0 + kq);
        }
        // Load B tile [32 x 128]
#pragma unroll
        for (int s = 0; s < 4; ++s) {
            int slot = tid + 256 * s;
            int kk   = slot >> 5;
            int cq   = (slot & 31) << 2;
            *(float4*)&Bs[kk][cq] =
                *(const float4*)(w + (size_t)(k0 + kk) * ldw + n0 + cq);
        }
        __syncthreads();
#pragma unroll
        for (int k = 0; k < 32; k += 2) {
            // B rows k and k+1, 4 cols each -> 2 packed pairs each (free fold)
            float4 b0 = *(const float4*)&Bs[k][tx << 2];
            float4 b1 = *(const float4*)&Bs[k + 1][tx << 2];
            u64 b0p0 = pack2(b0.x, b0.y), b0p1 = pack2(b0.z, b0.w);
            u64 b1p0 = pack2(b1.x, b1.y), b1p1 = pack2(b1.z, b1.w);
            // A: 8 rows, (k, k+1) pair per row (warp-broadcast LDS.64)
            float2 a01[8];
#pragma unroll
            for (int i = 0; i < 8; ++i)
                a01[i] = *(const float2*)&As[(ty << 3) + i][k];
#pragma unroll
            for (int i = 0; i < 8; ++i) {
                u64 aa0 = pack2(a01[i].x, a01[i].x);
                u64 aa1 = pack2(a01[i].y, a01[i].y);
                ffma2(acc2[i][0], aa0, b0p0);
                ffma2(acc2[i][1], aa0, b0p1);
                ffma2(acc2[i][0], aa1, b1p0);
                ffma2(acc2[i][1], aa1, b1p1);
            }
        }
    }
}

// ---------------------------------------------------------------------------
// Kernel 1: QKV projection. grid = (9, 2048). One window (64 rows) per CTA.y.
// ---------------------------------------------------------------------------
__global__ __launch_bounds__(256, 2) void qkv_kernel(
    const float* __restrict__ x, const float* __restrict__ w,
    const float* __restrict__ bias)
{
    __shared__ float As[64][32];
    __shared__ float Bs[32][128];
    __shared__ const float* rowptr[64];
    const int tid = threadIdx.x;
    const int win = blockIdx.y;
    const int n0  = blockIdx.x * 128;

    if (tid < 64) {
        int img = win >> 6, wi = win & 63, wr = wi >> 3, wc = wi & 7;
        int ri = tid >> 3, ci = tid & 7;
        int gr = (wr * 8 + ri + 4) & 63;
        int gc = (wc * 8 + ci + 4) & 63;
        rowptr[tid] = x + (((size_t)img * 64 + gr) * 64 + gc) * C;
    }

    u64 acc2[8][2];
#pragma unroll
    for (int i = 0; i < 8; ++i) { acc2[i][0] = 0ull; acc2[i][1] = 0ull; }

    gemm_body(rowptr, w, NQKV, n0, tid, acc2, As, Bs);

    const int tx = tid & 31, ty = tid >> 5;
    const float4 bb = *(const float4*)&bias[n0 + (tx << 2)];
#pragma unroll
    for (int i = 0; i < 8; ++i) {
        size_t m = (size_t)win * D + (ty << 3) + i;
        float2 a0 = unpack2(acc2[i][0]);
        float2 a1 = unpack2(acc2[i][1]);
        float4 o = make_float4(a0.x + bb.x, a0.y + bb.y,
                               a1.x + bb.z, a1.y + bb.w);
        *(float4*)&g_qkv[m * NQKV + n0 + (tx << 2)] = o;
    }
}

// ---------------------------------------------------------------------------
// Kernel 2: attention per (window, head). grid = (2048, 12), 256 threads.
// ---------------------------------------------------------------------------
__global__ __launch_bounds__(256) void attn_kernel(const float* __restrict__ bt)
{
    __shared__ float qs[64][32];
    __shared__ float ks[64][36];
    __shared__ float vs[64][36];
    __shared__ float ps[64][68];
    __shared__ int   s_sum[64];
    __shared__ int   s_regn[64];
    __shared__ float s_bias[32];

    const int tid = threadIdx.x;
    const int win = blockIdx.x;
    const int h   = blockIdx.y;
    const float scale = 0.17677669529663687f;  // 1/sqrt(32)

    if (tid < 64) {
        int wi = win & 63, wr = wi >> 3, wc = wi & 7;
        int ri = tid >> 3, ci = tid & 7;
        s_sum[tid] = ri + ci;
        int gr = wr * 8 + ri, gc = wc * 8 + ci;
        int rb = gr < 56 ? 0 : (gr < 60 ? 1 : 2);
        int cb = gc < 56 ? 0 : (gc < 60 ? 1 : 2);
        s_regn[tid] = rb * 3 + cb;
    }
    if (tid >= 64 && tid < 93) {
        int u = tid - 64;                    // bias idx range is [15, 43]
        s_bias[u] = bt[(u + 15) * 12 + h];
    }

    const size_t base = ((size_t)win * D) * NQKV + (size_t)h * 32;
#pragma unroll
    for (int s = 0; s < 2; ++s) {
        int slot = tid + 256 * s;
        int row  = slot >> 3;
        int eq   = (slot & 7) << 2;
        const float* src = &g_qkv[base + (size_t)row * NQKV + eq];
        float4 q4 = *(const float4*)(src);
        q4.x *= scale; q4.y *= scale; q4.z *= scale; q4.w *= scale;
        *(float4*)&qs[row][eq] = q4;
        *(float4*)&ks[row][eq] = *(const float4*)(src + 384);
        *(float4*)&vs[row][eq] = *(const float4*)(src + 768);
    }
    __syncthreads();

    const int i  = tid >> 2;   // query row, 4 threads per row
    const int jg = tid & 3;
    u64 q2[16];
#pragma unroll
    for (int e = 0; e < 32; e += 4) {
        float4 qq = *(const float4*)&qs[i][e];
        q2[(e >> 1)]     = pack2(qq.x, qq.y);
        q2[(e >> 1) + 1] = pack2(qq.z, qq.w);
    }
    const int isum  = s_sum[i];
    const int iregn = s_regn[i];

    float sc[16];
    float mx = -1e30f;
#pragma unroll
    for (int jj = 0; jj < 16; ++jj) {
        int j = (jj << 2) + jg;
        u64 acc2 = 0ull;
#pragma unroll
        for (int e = 0; e < 32; e += 4) {
            float4 k4 = *(const float4*)&ks[j][e];
            ffma2(acc2, q2[(e >> 1)],     pack2(k4.x, k4.y));
            ffma2(acc2, q2[(e >> 1) + 1], pack2(k4.z, k4.w));
        }
        float2 ap = unpack2(acc2);
        float acc = ap.x + ap.y;
        acc += s_bias[isum - s_sum[j] + 14];
        if (iregn != s_regn[j]) acc -= 100.f;
        sc[jj] = acc;
        mx = fmaxf(mx, acc);
    }
    mx = fmaxf(mx, __shfl_xor_sync(0xffffffffu, mx, 1));
    mx = fmaxf(mx, __shfl_xor_sync(0xffffffffu, mx, 2));

    float sum = 0.f;
#pragma unroll
    for (int jj = 0; jj < 16; ++jj) {
        float e = __expf(sc[jj] - mx);
        sc[jj] = e;
        sum += e;
    }
    sum += __shfl_xor_sync(0xffffffffu, sum, 1);
    sum += __shfl_xor_sync(0xffffffffu, sum, 2);
    float inv = 1.f / sum;
#pragma unroll
    for (int jj = 0; jj < 16; ++jj) ps[i][(jj << 2) + jg] = sc[jj] * inv;
    __syncthreads();

    // out[i][e0..e0+7] = sum_j P[i][j] * v[j][e], packed f32x2
    const int e0 = (tid & 3) << 3;
    u64 o2[4] = {0ull, 0ull, 0ull, 0ull};
#pragma unroll 8
    for (int j = 0; j < 64; ++j) {
        float p = ps[i][j];
        u64 pp = pack2(p, p);
        float4 v0 = *(const float4*)&vs[j][e0];
        float4 v1 = *(const float4*)&vs[j][e0 + 4];
        ffma2(o2[0], pp, pack2(v0.x, v0.y));
        ffma2(o2[1], pp, pack2(v0.z, v0.w));
        ffma2(o2[2], pp, pack2(v1.x, v1.y));
        ffma2(o2[3], pp, pack2(v1.z, v1.w));
    }
    float2 r0 = unpack2(o2[0]), r1 = unpack2(o2[1]);
    float2 r2 = unpack2(o2[2]), r3 = unpack2(o2[3]);
    float* cp = &g_ctx[((size_t)win * D + i) * C + h * 32 + e0];
    *(float4*)cp       = make_float4(r0.x, r0.y, r1.x, r1.y);
    *(float4*)(cp + 4) = make_float4(r2.x, r2.y, r3.x, r3.y);
}

// ---------------------------------------------------------------------------
// Kernel 3: output projection + window-reverse + roll(+4,+4) scatter.
// grid = (3, 2048).
// ---------------------------------------------------------------------------
__global__ __launch_bounds__(256, 2) void proj_kernel(
    const float* __restrict__ w, const float* __restrict__ bias,
    float* __restrict__ out)
{
    __shared__ float As[64][32];
    __shared__ float Bs[32][128];
    __shared__ const float* rowptr[64];
    __shared__ float* outptr[64];
    const int tid = threadIdx.x;
    const int win = blockIdx.y;
    const int n0  = blockIdx.x * 128;

    if (tid < 64) {
        rowptr[tid] = &g_ctx[((size_t)win * D + tid) * C];
        int img = win >> 6, wi = win & 63, wr = wi >> 3, wc = wi & 7;
        int ri = tid >> 3, ci = tid & 7;
        int gr = (wr * 8 + ri + 4) & 63;   // window-reverse + roll(+4) == +4 mod 64
        int gc = (wc * 8 + ci + 4) & 63;
        outptr[tid] = out + (((size_t)img * 64 + gr) * 64 + gc) * C;
    }

    u64 acc2[8][2];
#pragma unroll
    for (int i = 0; i < 8; ++i) { acc2[i][0] = 0ull; acc2[i][1] = 0ull; }

    gemm_body(rowptr, w, C, n0, tid, acc2, As, Bs);

    const int tx = tid & 31, ty = tid >> 5;
    const float4 bb = *(const float4*)&bias[n0 + (tx << 2)];
#pragma unroll
    for (int i = 0; i < 8; ++i) {
        float2 a0 = unpack2(acc2[i][0]);
        float2 a1 = unpack2(acc2[i][1]);
        float4 o = make_float4(a0.x + bb.x, a0.y + bb.y,
                               a1.x + bb.z, a1.y + bb.w);
        *(float4*)(outptr[(ty << 3) + i] + n0 + (tx << 2)) = o;
    }
}

// ---------------------------------------------------------------------------
extern "C" void kernel_launch(void* const* d_in, const int* in_sizes, int n_in,
                              void* d_out, int out_size)
{
    (void)in_sizes; (void)n_in; (void)out_size;
    const float* x      = (const float*)d_in[0];
    const float* w_qkv  = (const float*)d_in[1];
    const float* b_qkv  = (const float*)d_in[2];
    const float* w_out  = (const float*)d_in[3];
    const float* b_out  = (const float*)d_in[4];
    const float* btab   = (const float*)d_in[5];
    float* out = (float*)d_out;

    qkv_kernel <<<dim3(9, NWIN),  256>>>(x, w_qkv, b_qkv);
    attn_kernel<<<dim3(NWIN, 12), 256>>>(btab);
    proj_kernel<<<dim3(3, NWIN),  256>>>(w_out, b_out, out);
}